// round 5
// baseline (speedup 1.0000x reference)
#include <cuda_runtime.h>
#include <cstdint>

#define N_NODES   8192
#define N_EDGES   131072
#define FEAT      512
#define HID       256
#define NGRAPH    64
#define HSTRIDE   1792              // total h_node width: 256 + 512 + 1024
#define WORDS     256               // 8192 bits / 32
#define ADJ1_STRIDE 160
#define ADJ2_STRIDE 2048

// ---------------- static device scratch (no allocations allowed) -------------
__device__ unsigned int g_bits[N_NODES * WORDS];          // adjacency bitset (count>=1)
__device__ int          g_selfcnt[N_NODES];               // self-loop multiplicity
__device__ float        g_dinv1[N_NODES];
__device__ float        g_dinv2[N_NODES];
__device__ int          g_cnt1[N_NODES];
__device__ int          g_cnt2[N_NODES];
__device__ uint16_t     g_adj1[N_NODES * ADJ1_STRIDE];    // 1-hop neighbor lists
__device__ uint16_t     g_adj2[(size_t)N_NODES * ADJ2_STRIDE]; // strict 2-hop lists
__device__ float        g_H[(size_t)N_NODES * HSTRIDE];   // [r0 | h1a | h1b | h2a | h2b]
__device__ float        g_pool[NGRAPH * HSTRIDE];
__device__ int          g_start[NGRAPH];
__device__ int          g_end[NGRAPH];
__device__ int          g_ei64;                           // edge_index is int64
__device__ int          g_bat64;                          // batch is int64

// ---------------- 0) dtype detection ----------------------------------------
// If an index array is int64 with values < 8192, every odd little-endian
// 32-bit word is 0. With int32 data the odd words are other (random) indices,
// so 128 consecutive zero odd-words is conclusive.
__global__ void k_detect(const int* __restrict__ ei, const int* __restrict__ bat) {
    if (threadIdx.x == 0) {
        int ok = 1;
        for (int k = 0; k < 128; k++)
            if (ei[2 * k + 1] != 0) { ok = 0; break; }
        g_ei64 = ok;
        ok = 1;
        for (int k = 0; k < 128; k++)
            if (bat[2 * k + 1] != 0) { ok = 0; break; }
        g_bat64 = ok;
    }
}

// ---------------- 1) clear accumulators -------------------------------------
__global__ void k_zero() {
    int idx = blockIdx.x * blockDim.x + threadIdx.x;
    int stride = gridDim.x * blockDim.x;
    for (int i = idx; i < N_NODES * WORDS; i += stride) g_bits[i] = 0u;
    if (idx < N_NODES) g_selfcnt[idx] = 0;
    if (idx < NGRAPH) { g_start[idx] = 0x7fffffff; g_end[idx] = 0; }
}

// ---------------- 2) scatter edges into bitset ------------------------------
__global__ void k_edges(const int* __restrict__ ei) {
    int e = blockIdx.x * blockDim.x + threadIdx.x;
    if (e >= N_EDGES) return;
    int r, c;
    if (g_ei64) {
        r = ei[2 * e];                    // low word of int64
        c = ei[2 * (N_EDGES + e)];
    } else {
        r = ei[e];
        c = ei[N_EDGES + e];
    }
    if ((unsigned)r >= N_NODES || (unsigned)c >= N_NODES) return;  // safety
    atomicOr(&g_bits[r * WORDS + (c >> 5)], 1u << (c & 31));
    if (r == c) atomicAdd(&g_selfcnt[r], 1);
}

// ---------------- 3) boolean A@A, masks, degrees, CSR lists -----------------
// One block per row i. Thread t owns bit-word t (columns t*32..t*32+31).
__global__ void k_build() {
    int i = blockIdx.x;
    int t = threadIdx.x;
    __shared__ unsigned int sh[WORDS];
    __shared__ int pc1[256], pc2[256];

    sh[t] = g_bits[i * WORDS + t];
    __syncthreads();

    // acc = OR over k in row(i) of row(k)  ==  indicator of (A@A) > 0
    unsigned int acc = 0u;
    for (int w = 0; w < WORDS; w++) {
        unsigned int bits = sh[w];
        while (bits) {
            int b = __ffs(bits) - 1;
            bits &= bits - 1;
            int k = (w << 5) + b;
            acc |= g_bits[k * WORDS + t];      // coalesced 1KB row read (L2-resident)
        }
    }

    unsigned int myb  = sh[t];
    unsigned int diag = ((i >> 5) == t) ? (1u << (i & 31)) : 0u;

    // A1 = (A - I) > 0 : off-diag where count>=1; diagonal only if selfcount>=2
    unsigned int b1 = myb;
    if (g_selfcnt[i] < 2) b1 &= ~diag;
    // A2 = (ind(A@A) - A - I) > 0 : 2-hop reachable, no direct edge, not diagonal
    unsigned int b2 = acc & ~myb & ~diag;

    pc1[t] = __popc(b1);
    pc2[t] = __popc(b2);
    __syncthreads();

    // deterministic exclusive prefix (cheap, keeps neighbor order fixed)
    int o1 = 0, o2 = 0;
    for (int u = 0; u < t; u++) { o1 += pc1[u]; o2 += pc2[u]; }

    unsigned int bb = b1; int p = o1;
    while (bb) {
        int b = __ffs(bb) - 1; bb &= bb - 1;
        if (p < ADJ1_STRIDE) g_adj1[i * ADJ1_STRIDE + p] = (uint16_t)((t << 5) + b);
        p++;
    }
    bb = b2; p = o2;
    while (bb) {
        int b = __ffs(bb) - 1; bb &= bb - 1;
        if (p < ADJ2_STRIDE) g_adj2[(size_t)i * ADJ2_STRIDE + p] = (uint16_t)((t << 5) + b);
        p++;
    }

    if (t == 255) {
        int c1 = o1 + pc1[255]; if (c1 > ADJ1_STRIDE) c1 = ADJ1_STRIDE;
        int c2 = o2 + pc2[255]; if (c2 > ADJ2_STRIDE) c2 = ADJ2_STRIDE;
        g_cnt1[i] = c1;
        g_cnt2[i] = c2;
        g_dinv1[i] = (c1 > 0) ? rsqrtf((float)c1) : 0.f;
        g_dinv2[i] = (c2 > 0) ? rsqrtf((float)c2) : 0.f;
    }
}

// ---------------- 4) embed GEMM: H[:,0:256] = relu(x @ w_embed) -------------
// 64x64 tile, 16x16 threads, 4x4 register tile, K-tile 16.
__global__ void k_embed(const float* __restrict__ x, const float* __restrict__ w) {
    __shared__ float As[16][65];   // [kk][m], padded
    __shared__ float Bs[16][64];   // [kk][n]
    int t  = threadIdx.x;
    int tx = t & 15, ty = t >> 4;
    int row0 = blockIdx.x * 64;
    int col0 = blockIdx.y * 64;

    float acc[4][4];
    #pragma unroll
    for (int u = 0; u < 4; u++)
        #pragma unroll
        for (int v = 0; v < 4; v++) acc[u][v] = 0.f;

    for (int k0 = 0; k0 < FEAT; k0 += 16) {
        #pragma unroll
        for (int l = t; l < 64 * 16; l += 256) {
            int m = l >> 4, kk = l & 15;
            As[kk][m] = x[(size_t)(row0 + m) * FEAT + k0 + kk];
        }
        #pragma unroll
        for (int l = t; l < 16 * 64; l += 256) {
            int kk = l >> 6, n = l & 63;
            Bs[kk][n] = w[(size_t)(k0 + kk) * HID + col0 + n];
        }
        __syncthreads();
        #pragma unroll
        for (int kk = 0; kk < 16; kk++) {
            float a[4], b[4];
            #pragma unroll
            for (int u = 0; u < 4; u++) a[u] = As[kk][ty * 4 + u];
            #pragma unroll
            for (int v = 0; v < 4; v++) b[v] = Bs[kk][tx * 4 + v];
            #pragma unroll
            for (int u = 0; u < 4; u++)
                #pragma unroll
                for (int v = 0; v < 4; v++) acc[u][v] += a[u] * b[v];
        }
        __syncthreads();
    }
    #pragma unroll
    for (int u = 0; u < 4; u++)
        #pragma unroll
        for (int v = 0; v < 4; v++) {
            int r = row0 + ty * 4 + u;
            int c = col0 + tx * 4 + v;
            g_H[(size_t)r * HSTRIDE + c] = fmaxf(acc[u][v], 0.f);
        }
}

// ---------------- 5) SpMM: out = relu( dinv_i * sum_j dinv_j * H_in[j] ) ----
// One block per row. Thread t owns column t (and t+256 when NV==2).
// 8-wide neighbor batches keep ~8-16 independent LDGs in flight per thread.
template <int NV>
__global__ void k_spmm(int useA2, int in_off, int out_off) {
    const uint16_t* __restrict__ adj  = useA2 ? g_adj2 : g_adj1;
    const int       astr = useA2 ? ADJ2_STRIDE : ADJ1_STRIDE;
    const int* __restrict__   cnt  = useA2 ? g_cnt2 : g_cnt1;
    const float* __restrict__ dinv = useA2 ? g_dinv2 : g_dinv1;

    int i = blockIdx.x;
    int t = threadIdx.x;
    float si = dinv[i];
    float acc0 = 0.f, acc1 = 0.f;

    if (si != 0.f) {
        int n = cnt[i];
        const uint16_t* __restrict__ a = adj + (size_t)i * astr;
        const float* __restrict__ base = g_H + in_off + t;
        int k = 0;
        for (; k + 8 <= n; k += 8) {
            int   j[8];
            float c[8];
            const float* p[8];
            #pragma unroll
            for (int u = 0; u < 8; u++) j[u] = a[k + u];
            #pragma unroll
            for (int u = 0; u < 8; u++) { c[u] = dinv[j[u]]; p[u] = base + j[u] * HSTRIDE; }
            float v0[8];
            #pragma unroll
            for (int u = 0; u < 8; u++) v0[u] = p[u][0];
            if (NV == 2) {
                float v1[8];
                #pragma unroll
                for (int u = 0; u < 8; u++) v1[u] = p[u][256];
                #pragma unroll
                for (int u = 0; u < 8; u++) acc1 += c[u] * v1[u];
            }
            #pragma unroll
            for (int u = 0; u < 8; u++) acc0 += c[u] * v0[u];
        }
        for (; k < n; k++) {
            int jj = a[k];
            float cc = dinv[jj];
            const float* pp = base + jj * HSTRIDE;
            acc0 += cc * pp[0];
            if (NV == 2) acc1 += cc * pp[256];
        }
        acc0 *= si;
        acc1 *= si;
    }
    float* o = g_H + (size_t)i * HSTRIDE + out_off + t;
    o[0] = fmaxf(acc0, 0.f);
    if (NV == 2) o[256] = fmaxf(acc1, 0.f);
}

// ---------------- 6) segment boundaries (batch is sorted) -------------------
__global__ void k_seg(const int* __restrict__ batch) {
    int i = blockIdx.x * blockDim.x + threadIdx.x;
    if (i < N_NODES) {
        int g = g_bat64 ? batch[2 * i] : batch[i];
        if ((unsigned)g < NGRAPH) {
            atomicMin(&g_start[g], i);
            atomicMax(&g_end[g], i + 1);
        }
    }
}

// ---------------- 7) mean pool ----------------------------------------------
__global__ void k_pool() {
    int g = blockIdx.x;
    int c = blockIdx.y * 256 + threadIdx.x;   // 7 * 256 = 1792 exactly
    int s = g_start[g], e = g_end[g];
    const float* __restrict__ H = g_H;
    float sum = 0.f;
    int cnt = 0;
    if (e > s) {
        cnt = e - s;
        for (int i = s; i < e; i++) sum += H[(size_t)i * HSTRIDE + c];
    }
    g_pool[g * HSTRIDE + c] = sum / (float)(cnt > 0 ? cnt : 1);
}

// ---------------- 8) output GEMM + bias + loss tail -------------------------
__global__ void k_out(const float* __restrict__ Wo, const float* __restrict__ bo,
                      float* __restrict__ out) {
    int g = blockIdx.x;
    int h = threadIdx.x;
    float acc = bo[h];
    const float* pg = g_pool + g * HSTRIDE;
    #pragma unroll 4
    for (int d = 0; d < HSTRIDE; d++)
        acc += pg[d] * Wo[(size_t)d * HID + h];
    out[g * HID + h] = acc;
}

__global__ void k_tail(float* out, int out_size) {
    for (int idx = NGRAPH * HID + threadIdx.x; idx < out_size; idx += 256)
        out[idx] = 0.f;   // additional_loss = 0.0 (and any padding)
}

// ---------------- launch ----------------------------------------------------
extern "C" void kernel_launch(void* const* d_in, const int* in_sizes, int n_in,
                              void* d_out, int out_size) {
    // Map inputs by element count (all counts are distinct) for robustness.
    const float* x = nullptr; const float* we = nullptr;
    const float* Wo = nullptr; const float* bo = nullptr;
    const int* ei = nullptr; const int* bat = nullptr;
    for (int i = 0; i < n_in; i++) {
        switch (in_sizes[i]) {
            case N_NODES * FEAT:   x  = (const float*)d_in[i]; break; // 4194304
            case 2 * N_EDGES:      ei = (const int*)d_in[i];   break; // 262144
            case N_NODES:          bat = (const int*)d_in[i];  break; // 8192
            case FEAT * HID:       we = (const float*)d_in[i]; break; // 131072
            case HSTRIDE * HID:    Wo = (const float*)d_in[i]; break; // 458752
            case HID:              bo = (const float*)d_in[i]; break; // 256
            default: break;
        }
    }
    float* out = (float*)d_out;

    k_detect<<<1, 32>>>(ei, bat);
    k_zero<<<4096, 256>>>();
    k_edges<<<N_EDGES / 256, 256>>>(ei);
    k_seg<<<N_NODES / 256, 256>>>(bat);
    k_build<<<N_NODES, 256>>>();
    k_embed<<<dim3(N_NODES / 64, HID / 64), 256>>>(x, we);

    // hop 1: input H[:,0:256] -> A1n out at 256, A2n out at 512
    k_spmm<1><<<N_NODES, 256>>>(0, 0, 256);
    k_spmm<1><<<N_NODES, 256>>>(1, 0, 512);
    // hop 2: input H[:,256:768] -> A1n out at 768, A2n out at 1280
    k_spmm<2><<<N_NODES, 256>>>(0, 256, 768);
    k_spmm<2><<<N_NODES, 256>>>(1, 256, 1280);

    k_pool<<<dim3(NGRAPH, HSTRIDE / 256), 256>>>();
    k_out<<<NGRAPH, HID>>>(Wo, bo, out);
    k_tail<<<1, 256>>>(out, out_size);
}

// round 8
// speedup vs baseline: 1.8606x; 1.8606x over previous
#include <cuda_runtime.h>
#include <cuda_fp16.h>
#include <cstdint>

#define N_NODES   8192
#define N_EDGES   131072
#define FEAT      512
#define HID       256
#define NGRAPH    64
#define HSTRIDE   1792              // total h_node width: 256 + 512 + 1024
#define WORDS     256               // 8192 bits / 32
#define ADJ1_STRIDE 160
#define ADJ2_STRIDE 2048

// ---------------- static device scratch (no allocations allowed) -------------
__device__ unsigned int g_bits[N_NODES * WORDS];          // adjacency bitset (count>=1)
__device__ int          g_selfcnt[N_NODES];               // self-loop multiplicity
__device__ float        g_dinv1[N_NODES];
__device__ float        g_dinv2[N_NODES];
__device__ int          g_cnt1[N_NODES];
__device__ int          g_cnt2[N_NODES];
__device__ uint16_t     g_adj1[N_NODES * ADJ1_STRIDE];    // 1-hop neighbor lists
__device__ uint16_t     g_adj2[(size_t)N_NODES * ADJ2_STRIDE]; // strict 2-hop lists
__device__ float        g_H[(size_t)N_NODES * HSTRIDE];   // fp32 [r0 | h1a h1b | h2a h2b]
__device__ __half       g_Hh1[(size_t)N_NODES * 256];     // half copy of r0 (hop1 input)
__device__ __half       g_Hh2[(size_t)N_NODES * 512];     // half copy of hop1 out (hop2 input)
__device__ float        g_pool[NGRAPH * HSTRIDE];
__device__ int          g_start[NGRAPH];
__device__ int          g_end[NGRAPH];
__device__ int          g_ei64;                           // edge_index is int64
__device__ int          g_bat64;                          // batch is int64

// ---------------- 0) dtype detection ----------------------------------------
// int64 arrays with values < 8192 have every odd little-endian 32-bit word 0.
__global__ void k_detect(const int* __restrict__ ei, const int* __restrict__ bat) {
    if (threadIdx.x == 0) {
        int ok = 1;
        for (int k = 0; k < 128; k++)
            if (ei[2 * k + 1] != 0) { ok = 0; break; }
        g_ei64 = ok;
        ok = 1;
        for (int k = 0; k < 128; k++)
            if (bat[2 * k + 1] != 0) { ok = 0; break; }
        g_bat64 = ok;
    }
}

// ---------------- 1) clear accumulators -------------------------------------
__global__ void k_zero() {
    int idx = blockIdx.x * blockDim.x + threadIdx.x;
    int stride = gridDim.x * blockDim.x;
    for (int i = idx; i < N_NODES * WORDS; i += stride) g_bits[i] = 0u;
    if (idx < N_NODES) g_selfcnt[idx] = 0;
    if (idx < NGRAPH) { g_start[idx] = 0x7fffffff; g_end[idx] = 0; }
}

// ---------------- 2) scatter edges into bitset ------------------------------
__global__ void k_edges(const int* __restrict__ ei) {
    int e = blockIdx.x * blockDim.x + threadIdx.x;
    if (e >= N_EDGES) return;
    int r, c;
    if (g_ei64) {
        r = ei[2 * e];                    // low word of int64
        c = ei[2 * (N_EDGES + e)];
    } else {
        r = ei[e];
        c = ei[N_EDGES + e];
    }
    if ((unsigned)r >= N_NODES || (unsigned)c >= N_NODES) return;  // safety
    atomicOr(&g_bits[r * WORDS + (c >> 5)], 1u << (c & 31));
    if (r == c) atomicAdd(&g_selfcnt[r], 1);
}

// ---------------- 3) boolean A@A, masks, degrees, CSR lists -----------------
// One block per row i. Thread t owns bit-word t (columns t*32..t*32+31).
__global__ void k_build() {
    int i = blockIdx.x;
    int t = threadIdx.x;
    __shared__ unsigned int sh[WORDS];
    __shared__ int pc1[256], pc2[256];

    sh[t] = g_bits[i * WORDS + t];
    __syncthreads();

    // acc = OR over k in row(i) of row(k)  ==  indicator of (A@A) > 0
    unsigned int acc = 0u;
    for (int w = 0; w < WORDS; w++) {
        unsigned int bits = sh[w];
        while (bits) {
            int b = __ffs(bits) - 1;
            bits &= bits - 1;
            int k = (w << 5) + b;
            acc |= g_bits[k * WORDS + t];      // coalesced 1KB row read (L2-resident)
        }
    }

    unsigned int myb  = sh[t];
    unsigned int diag = ((i >> 5) == t) ? (1u << (i & 31)) : 0u;

    // A1 = (A - I) > 0 : off-diag where count>=1; diagonal only if selfcount>=2
    unsigned int b1 = myb;
    if (g_selfcnt[i] < 2) b1 &= ~diag;
    // A2 = (ind(A@A) - A - I) > 0 : 2-hop reachable, no direct edge, not diagonal
    unsigned int b2 = acc & ~myb & ~diag;

    pc1[t] = __popc(b1);
    pc2[t] = __popc(b2);
    __syncthreads();

    // deterministic exclusive prefix (cheap, keeps neighbor order fixed)
    int o1 = 0, o2 = 0;
    for (int u = 0; u < t; u++) { o1 += pc1[u]; o2 += pc2[u]; }

    unsigned int bb = b1; int p = o1;
    while (bb) {
        int b = __ffs(bb) - 1; bb &= bb - 1;
        if (p < ADJ1_STRIDE) g_adj1[i * ADJ1_STRIDE + p] = (uint16_t)((t << 5) + b);
        p++;
    }
    bb = b2; p = o2;
    while (bb) {
        int b = __ffs(bb) - 1; bb &= bb - 1;
        if (p < ADJ2_STRIDE) g_adj2[(size_t)i * ADJ2_STRIDE + p] = (uint16_t)((t << 5) + b);
        p++;
    }

    if (t == 255) {
        int c1 = o1 + pc1[255]; if (c1 > ADJ1_STRIDE) c1 = ADJ1_STRIDE;
        int c2 = o2 + pc2[255]; if (c2 > ADJ2_STRIDE) c2 = ADJ2_STRIDE;
        g_cnt1[i] = c1;
        g_cnt2[i] = c2;
        g_dinv1[i] = (c1 > 0) ? rsqrtf((float)c1) : 0.f;
        g_dinv2[i] = (c2 > 0) ? rsqrtf((float)c2) : 0.f;
    }
}

// ---------------- 4) embed GEMM: H[:,0:256] = relu(x @ w_embed) -------------
// 64x64 tile, 16x16 threads, 4x4 register tile, K-tile 16.
// Writes fp32 into g_H and a half copy into g_Hh1 (hop1 input).
__global__ void k_embed(const float* __restrict__ x, const float* __restrict__ w) {
    __shared__ float As[16][65];   // [kk][m], padded
    __shared__ float Bs[16][64];   // [kk][n]
    int t  = threadIdx.x;
    int tx = t & 15, ty = t >> 4;
    int row0 = blockIdx.x * 64;
    int col0 = blockIdx.y * 64;

    float acc[4][4];
    #pragma unroll
    for (int u = 0; u < 4; u++)
        #pragma unroll
        for (int v = 0; v < 4; v++) acc[u][v] = 0.f;

    for (int k0 = 0; k0 < FEAT; k0 += 16) {
        #pragma unroll
        for (int l = t; l < 64 * 16; l += 256) {
            int m = l >> 4, kk = l & 15;
            As[kk][m] = x[(size_t)(row0 + m) * FEAT + k0 + kk];
        }
        #pragma unroll
        for (int l = t; l < 16 * 64; l += 256) {
            int kk = l >> 6, n = l & 63;
            Bs[kk][n] = w[(size_t)(k0 + kk) * HID + col0 + n];
        }
        __syncthreads();
        #pragma unroll
        for (int kk = 0; kk < 16; kk++) {
            float a[4], b[4];
            #pragma unroll
            for (int u = 0; u < 4; u++) a[u] = As[kk][ty * 4 + u];
            #pragma unroll
            for (int v = 0; v < 4; v++) b[v] = Bs[kk][tx * 4 + v];
            #pragma unroll
            for (int u = 0; u < 4; u++)
                #pragma unroll
                for (int v = 0; v < 4; v++) acc[u][v] += a[u] * b[v];
        }
        __syncthreads();
    }
    #pragma unroll
    for (int u = 0; u < 4; u++) {
        int r = row0 + ty * 4 + u;
        int c = col0 + tx * 4;
        float r0 = fmaxf(acc[u][0], 0.f);
        float r1 = fmaxf(acc[u][1], 0.f);
        float r2 = fmaxf(acc[u][2], 0.f);
        float r3 = fmaxf(acc[u][3], 0.f);
        float* o = g_H + (size_t)r * HSTRIDE + c;
        o[0] = r0; o[1] = r1; o[2] = r2; o[3] = r3;
        __half2* hh = reinterpret_cast<__half2*>(&g_Hh1[(size_t)r * 256 + c]);
        hh[0] = __floats2half2_rn(r0, r1);
        hh[1] = __floats2half2_rn(r2, r3);
    }
}

// ---------------- 5a) hop-1 SpMM (half2 gathers from g_Hh1, width 256) ------
// 128 threads/row; thread t owns column pair (2t, 2t+1). gridDim.y: 0=A1, 1=A2.
// fp32 result -> g_H; half copy -> g_Hh2 (hop-2 input).
__global__ void k_spmm1() {
    int i = blockIdx.x;
    int t = threadIdx.x;                 // 0..127
    int useA2 = blockIdx.y;
    const uint16_t* __restrict__ adj  = useA2 ? g_adj2 : g_adj1;
    const int       astr = useA2 ? ADJ2_STRIDE : ADJ1_STRIDE;
    const int* __restrict__   cnt  = useA2 ? g_cnt2 : g_cnt1;
    const float* __restrict__ dinv = useA2 ? g_dinv2 : g_dinv1;
    int out_off = useA2 ? 512 : 256;

    float si = dinv[i];
    float a0 = 0.f, a1 = 0.f;

    if (si != 0.f) {
        int n = cnt[i];
        const uint16_t* __restrict__ a = adj + (size_t)i * astr;
        const __half2* __restrict__ base =
            reinterpret_cast<const __half2*>(g_Hh1) + t;   // row stride 128 half2
        int k = 0;
        for (; k + 8 <= n; k += 8) {
            int     j[8];
            float   c[8];
            __half2 v[8];
            #pragma unroll
            for (int u = 0; u < 8; u++) j[u] = a[k + u];
            #pragma unroll
            for (int u = 0; u < 8; u++) { c[u] = dinv[j[u]]; v[u] = base[j[u] * 128]; }
            #pragma unroll
            for (int u = 0; u < 8; u++) {
                float2 f = __half22float2(v[u]);
                a0 += c[u] * f.x;
                a1 += c[u] * f.y;
            }
        }
        for (; k < n; k++) {
            int jj = a[k];
            float cc = dinv[jj];
            float2 f = __half22float2(base[jj * 128]);
            a0 += cc * f.x;
            a1 += cc * f.y;
        }
        a0 *= si; a1 *= si;
    }
    a0 = fmaxf(a0, 0.f);
    a1 = fmaxf(a1, 0.f);
    // fp32 out (float2-aligned: offsets even)
    float2* o = reinterpret_cast<float2*>(g_H + (size_t)i * HSTRIDE + out_off) + t;
    *o = make_float2(a0, a1);
    // half copy for hop2 input: A1 -> pairs [0,128), A2 -> pairs [128,256)
    __half2* hh = reinterpret_cast<__half2*>(g_Hh2) + (size_t)i * 256 + (useA2 ? 128 + t : t);
    *hh = __floats2half2_rn(a0, a1);
}

// ---------------- 5b) hop-2 SpMM (half2 gathers from g_Hh2, width 512) ------
// 128 threads/row; thread t owns pairs t and t+128 (cols 2t,2t+1, 256+2t, 256+2t+1).
__global__ void k_spmm2() {
    int i = blockIdx.x;
    int t = threadIdx.x;                 // 0..127
    int useA2 = blockIdx.y;
    const uint16_t* __restrict__ adj  = useA2 ? g_adj2 : g_adj1;
    const int       astr = useA2 ? ADJ2_STRIDE : ADJ1_STRIDE;
    const int* __restrict__   cnt  = useA2 ? g_cnt2 : g_cnt1;
    const float* __restrict__ dinv = useA2 ? g_dinv2 : g_dinv1;
    int out_off = useA2 ? 1280 : 768;

    float si = dinv[i];
    float a0 = 0.f, a1 = 0.f, a2 = 0.f, a3 = 0.f;

    if (si != 0.f) {
        int n = cnt[i];
        const uint16_t* __restrict__ a = adj + (size_t)i * astr;
        const __half2* __restrict__ base =
            reinterpret_cast<const __half2*>(g_Hh2) + t;   // row stride 256 half2
        int k = 0;
        for (; k + 8 <= n; k += 8) {
            int     j[8];
            float   c[8];
            __half2 v0[8], v1[8];
            #pragma unroll
            for (int u = 0; u < 8; u++) j[u] = a[k + u];
            #pragma unroll
            for (int u = 0; u < 8; u++) {
                c[u]  = dinv[j[u]];
                const __half2* p = base + j[u] * 256;
                v0[u] = p[0];
                v1[u] = p[128];
            }
            #pragma unroll
            for (int u = 0; u < 8; u++) {
                float2 f0 = __half22float2(v0[u]);
                float2 f1 = __half22float2(v1[u]);
                a0 += c[u] * f0.x;
                a1 += c[u] * f0.y;
                a2 += c[u] * f1.x;
                a3 += c[u] * f1.y;
            }
        }
        for (; k < n; k++) {
            int jj = a[k];
            float cc = dinv[jj];
            const __half2* p = base + jj * 256;
            float2 f0 = __half22float2(p[0]);
            float2 f1 = __half22float2(p[128]);
            a0 += cc * f0.x;
            a1 += cc * f0.y;
            a2 += cc * f1.x;
            a3 += cc * f1.y;
        }
        a0 *= si; a1 *= si; a2 *= si; a3 *= si;
    }
    float2* oA = reinterpret_cast<float2*>(g_H + (size_t)i * HSTRIDE + out_off) + t;
    float2* oB = reinterpret_cast<float2*>(g_H + (size_t)i * HSTRIDE + out_off + 256) + t;
    *oA = make_float2(fmaxf(a0, 0.f), fmaxf(a1, 0.f));
    *oB = make_float2(fmaxf(a2, 0.f), fmaxf(a3, 0.f));
}

// ---------------- 6) segment boundaries (batch is sorted) -------------------
__global__ void k_seg(const int* __restrict__ batch) {
    int i = blockIdx.x * blockDim.x + threadIdx.x;
    if (i < N_NODES) {
        int g = g_bat64 ? batch[2 * i] : batch[i];
        if ((unsigned)g < NGRAPH) {
            atomicMin(&g_start[g], i);
            atomicMax(&g_end[g], i + 1);
        }
    }
}

// ---------------- 7) mean pool ----------------------------------------------
__global__ void k_pool() {
    int g = blockIdx.x;
    int c = blockIdx.y * 256 + threadIdx.x;   // 7 * 256 = 1792 exactly
    int s = g_start[g], e = g_end[g];
    const float* __restrict__ H = g_H;
    float sum = 0.f;
    int cnt = 0;
    if (e > s) {
        cnt = e - s;
        for (int i = s; i < e; i++) sum += H[(size_t)i * HSTRIDE + c];
    }
    g_pool[g * HSTRIDE + c] = sum / (float)(cnt > 0 ? cnt : 1);
}

// ---------------- 8) output GEMM + bias + loss tail -------------------------
__global__ void k_out(const float* __restrict__ Wo, const float* __restrict__ bo,
                      float* __restrict__ out) {
    int g = blockIdx.x;
    int h = threadIdx.x;
    float acc = bo[h];
    const float* pg = g_pool + g * HSTRIDE;
    #pragma unroll 4
    for (int d = 0; d < HSTRIDE; d++)
        acc += pg[d] * Wo[(size_t)d * HID + h];
    out[g * HID + h] = acc;
}

__global__ void k_tail(float* out, int out_size) {
    for (int idx = NGRAPH * HID + threadIdx.x; idx < out_size; idx += 256)
        out[idx] = 0.f;   // additional_loss = 0.0 (and any padding)
}

// ---------------- launch ----------------------------------------------------
extern "C" void kernel_launch(void* const* d_in, const int* in_sizes, int n_in,
                              void* d_out, int out_size) {
    // Map inputs by element count (all counts are distinct) for robustness.
    const float* x = nullptr; const float* we = nullptr;
    const float* Wo = nullptr; const float* bo = nullptr;
    const int* ei = nullptr; const int* bat = nullptr;
    for (int i = 0; i < n_in; i++) {
        switch (in_sizes[i]) {
            case N_NODES * FEAT:   x  = (const float*)d_in[i]; break; // 4194304
            case 2 * N_EDGES:      ei = (const int*)d_in[i];   break; // 262144
            case N_NODES:          bat = (const int*)d_in[i];  break; // 8192
            case FEAT * HID:       we = (const float*)d_in[i]; break; // 131072
            case HSTRIDE * HID:    Wo = (const float*)d_in[i]; break; // 458752
            case HID:              bo = (const float*)d_in[i]; break; // 256
            default: break;
        }
    }
    float* out = (float*)d_out;

    k_detect<<<1, 32>>>(ei, bat);
    k_zero<<<4096, 256>>>();
    k_edges<<<N_EDGES / 256, 256>>>(ei);
    k_seg<<<N_NODES / 256, 256>>>(bat);
    k_build<<<N_NODES, 256>>>();
    k_embed<<<dim3(N_NODES / 64, HID / 64), 256>>>(x, we);

    // hop 1: half2 gathers from g_Hh1; y=0 -> A1 (out 256), y=1 -> A2 (out 512)
    k_spmm1<<<dim3(N_NODES, 2), 128>>>();
    // hop 2: half2 gathers from g_Hh2; y=0 -> A1 (out 768), y=1 -> A2 (out 1280)
    k_spmm2<<<dim3(N_NODES, 2), 128>>>();

    k_pool<<<dim3(NGRAPH, HSTRIDE / 256), 256>>>();
    k_out<<<NGRAPH, HID>>>(Wo, bo, out);
    k_tail<<<1, 256>>>(out, out_size);
}

// round 11
// speedup vs baseline: 2.1682x; 1.1653x over previous
#include <cuda_runtime.h>
#include <cuda_fp16.h>
#include <cstdint>

#define N_NODES   8192
#define N_EDGES   131072
#define FEAT      512
#define HID       256
#define NGRAPH    64
#define HSTRIDE   1792              // total h_node width: 256 + 512 + 1024
#define WORDS     256               // 8192 bits / 32
#define ADJ1_STRIDE 160
#define ADJ2_STRIDE 2048
#define NB_CAP    2048              // compacted 1-hop list capacity (smem)

// ---------------- static device scratch (no allocations allowed) -------------
__device__ unsigned int g_bits[N_NODES * WORDS];          // adjacency bitset (count>=1)
__device__ int          g_selfcnt[N_NODES];               // self-loop multiplicity
__device__ float        g_dinv1[N_NODES];
__device__ float        g_dinv2[N_NODES];
__device__ int          g_cnt1[N_NODES];
__device__ int          g_cnt2[N_NODES];
__device__ uint16_t     g_adj1[N_NODES * ADJ1_STRIDE];    // 1-hop neighbor lists
__device__ uint16_t     g_adj2[(size_t)N_NODES * ADJ2_STRIDE]; // strict 2-hop lists
__device__ float        g_H[(size_t)N_NODES * HSTRIDE];   // fp32 [r0 | h1a h1b | h2a h2b]
__device__ __half       g_Hh1[(size_t)N_NODES * 256];     // half copy of r0 (hop1 input)
__device__ __half       g_Hh2[(size_t)N_NODES * 512];     // half copy of hop1 out (hop2 input)
__device__ float        g_pool[NGRAPH * HSTRIDE];
__device__ int          g_start[NGRAPH];
__device__ int          g_end[NGRAPH];
__device__ int          g_ei64;                           // edge_index is int64
__device__ int          g_bat64;                          // batch is int64

// ---------------- 1) setup: dtype detection + clear accumulators ------------
// int64 arrays with values < 8192 have every odd little-endian 32-bit word 0.
__global__ void k_setup(const int* __restrict__ ei, const int* __restrict__ bat) {
    int idx = blockIdx.x * blockDim.x + threadIdx.x;
    if (idx == 0) {
        int ok = 1;
        for (int k = 0; k < 128; k++)
            if (ei[2 * k + 1] != 0) { ok = 0; break; }
        g_ei64 = ok;
        ok = 1;
        for (int k = 0; k < 128; k++)
            if (bat[2 * k + 1] != 0) { ok = 0; break; }
        g_bat64 = ok;
    }
    int stride = gridDim.x * blockDim.x;
    for (int i = idx; i < N_NODES * WORDS; i += stride) g_bits[i] = 0u;
    if (idx < N_NODES) g_selfcnt[idx] = 0;
    if (idx < NGRAPH) { g_start[idx] = 0x7fffffff; g_end[idx] = 0; }
}

// ---------------- 2) scatter edges into bitset + segment bounds -------------
__global__ void k_scatter(const int* __restrict__ ei, const int* __restrict__ bat) {
    int e = blockIdx.x * blockDim.x + threadIdx.x;
    if (e < N_EDGES) {
        int r, c;
        if (g_ei64) {
            r = ei[2 * e];                    // low word of int64
            c = ei[2 * (N_EDGES + e)];
        } else {
            r = ei[e];
            c = ei[N_EDGES + e];
        }
        if ((unsigned)r < N_NODES && (unsigned)c < N_NODES) {   // safety
            atomicOr(&g_bits[r * WORDS + (c >> 5)], 1u << (c & 31));
            if (r == c) atomicAdd(&g_selfcnt[r], 1);
        }
    }
    if (e < N_NODES) {
        int g = g_bat64 ? bat[2 * e] : bat[e];
        if ((unsigned)g < NGRAPH) {
            atomicMin(&g_start[g], e);
            atomicMax(&g_end[g], e + 1);
        }
    }
}

// ---------------- 3) boolean A@A, masks, degrees, CSR lists -----------------
// One block per row i. Thread t owns bit-word t (columns t*32..t*32+31).
// Neighbor ids are compacted to smem once (order-free: consumed only by OR),
// so the OR-gather loop avoids the per-thread 256-word rescan.
__global__ void k_build() {
    int i = blockIdx.x;
    int t = threadIdx.x;
    __shared__ unsigned int sh[WORDS];
    __shared__ int pc1[256], pc2[256];
    __shared__ uint16_t nb[NB_CAP];
    __shared__ int nb_cnt;

    sh[t] = g_bits[i * WORDS + t];
    if (t == 0) nb_cnt = 0;
    __syncthreads();

    // compact neighbor list (order nondeterministic, OR is order-free)
    {
        unsigned int b = sh[t];
        int n = __popc(b);
        int pos = (n > 0) ? atomicAdd(&nb_cnt, n) : 0;
        while (b) {
            int bit = __ffs(b) - 1; b &= b - 1;
            if (pos < NB_CAP) nb[pos] = (uint16_t)((t << 5) + bit);
            pos++;
        }
    }
    __syncthreads();

    // acc = OR over k in row(i) of row(k)  ==  indicator of (A@A) > 0
    unsigned int acc = 0u;
    int m = nb_cnt;
    if (m <= NB_CAP) {
        int k = 0;
        for (; k + 4 <= m; k += 4) {
            int k0 = nb[k], k1 = nb[k + 1], k2 = nb[k + 2], k3 = nb[k + 3];
            unsigned int a0 = g_bits[k0 * WORDS + t];
            unsigned int a1 = g_bits[k1 * WORDS + t];
            unsigned int a2 = g_bits[k2 * WORDS + t];
            unsigned int a3 = g_bits[k3 * WORDS + t];
            acc |= a0 | a1 | a2 | a3;
        }
        for (; k < m; k++) acc |= g_bits[nb[k] * WORDS + t];
    } else {
        // exact fallback for pathological degree > NB_CAP
        for (int w = 0; w < WORDS; w++) {
            unsigned int bits = sh[w];
            while (bits) {
                int b = __ffs(bits) - 1; bits &= bits - 1;
                acc |= g_bits[((w << 5) + b) * WORDS + t];
            }
        }
    }

    unsigned int myb  = sh[t];
    unsigned int diag = ((i >> 5) == t) ? (1u << (i & 31)) : 0u;

    // A1 = (A - I) > 0 : off-diag where count>=1; diagonal only if selfcount>=2
    unsigned int b1 = myb;
    if (g_selfcnt[i] < 2) b1 &= ~diag;
    // A2 = (ind(A@A) - A - I) > 0 : 2-hop reachable, no direct edge, not diagonal
    unsigned int b2 = acc & ~myb & ~diag;

    pc1[t] = __popc(b1);
    pc2[t] = __popc(b2);
    __syncthreads();

    // deterministic exclusive prefix (keeps adjacency order fixed run-to-run)
    int o1 = 0, o2 = 0;
    for (int u = 0; u < t; u++) { o1 += pc1[u]; o2 += pc2[u]; }

    unsigned int bb = b1; int p = o1;
    while (bb) {
        int b = __ffs(bb) - 1; bb &= bb - 1;
        if (p < ADJ1_STRIDE) g_adj1[i * ADJ1_STRIDE + p] = (uint16_t)((t << 5) + b);
        p++;
    }
    bb = b2; p = o2;
    while (bb) {
        int b = __ffs(bb) - 1; bb &= bb - 1;
        if (p < ADJ2_STRIDE) g_adj2[(size_t)i * ADJ2_STRIDE + p] = (uint16_t)((t << 5) + b);
        p++;
    }

    if (t == 255) {
        int c1 = o1 + pc1[255]; if (c1 > ADJ1_STRIDE) c1 = ADJ1_STRIDE;
        int c2 = o2 + pc2[255]; if (c2 > ADJ2_STRIDE) c2 = ADJ2_STRIDE;
        g_cnt1[i] = c1;
        g_cnt2[i] = c2;
        g_dinv1[i] = (c1 > 0) ? rsqrtf((float)c1) : 0.f;
        g_dinv2[i] = (c2 > 0) ? rsqrtf((float)c2) : 0.f;
    }
}

// ---------------- 4) embed GEMM: H[:,0:256] = relu(x @ w_embed) -------------
// 64x64 tile, 16x16 threads, 4x4 register tile, K-tile 16.
// Writes fp32 into g_H and a half copy into g_Hh1 (hop1 input).
__global__ void k_embed(const float* __restrict__ x, const float* __restrict__ w) {
    __shared__ float As[16][65];   // [kk][m], padded
    __shared__ float Bs[16][64];   // [kk][n]
    int t  = threadIdx.x;
    int tx = t & 15, ty = t >> 4;
    int row0 = blockIdx.x * 64;
    int col0 = blockIdx.y * 64;

    float acc[4][4];
    #pragma unroll
    for (int u = 0; u < 4; u++)
        #pragma unroll
        for (int v = 0; v < 4; v++) acc[u][v] = 0.f;

    for (int k0 = 0; k0 < FEAT; k0 += 16) {
        #pragma unroll
        for (int l = t; l < 64 * 16; l += 256) {
            int m = l >> 4, kk = l & 15;
            As[kk][m] = x[(size_t)(row0 + m) * FEAT + k0 + kk];
        }
        #pragma unroll
        for (int l = t; l < 16 * 64; l += 256) {
            int kk = l >> 6, n = l & 63;
            Bs[kk][n] = w[(size_t)(k0 + kk) * HID + col0 + n];
        }
        __syncthreads();
        #pragma unroll
        for (int kk = 0; kk < 16; kk++) {
            float a[4], b[4];
            #pragma unroll
            for (int u = 0; u < 4; u++) a[u] = As[kk][ty * 4 + u];
            #pragma unroll
            for (int v = 0; v < 4; v++) b[v] = Bs[kk][tx * 4 + v];
            #pragma unroll
            for (int u = 0; u < 4; u++)
                #pragma unroll
                for (int v = 0; v < 4; v++) acc[u][v] += a[u] * b[v];
        }
        __syncthreads();
    }
    #pragma unroll
    for (int u = 0; u < 4; u++) {
        int r = row0 + ty * 4 + u;
        int c = col0 + tx * 4;
        float r0 = fmaxf(acc[u][0], 0.f);
        float r1 = fmaxf(acc[u][1], 0.f);
        float r2 = fmaxf(acc[u][2], 0.f);
        float r3 = fmaxf(acc[u][3], 0.f);
        float* o = g_H + (size_t)r * HSTRIDE + c;
        o[0] = r0; o[1] = r1; o[2] = r2; o[3] = r3;
        __half2* hh = reinterpret_cast<__half2*>(&g_Hh1[(size_t)r * 256 + c]);
        hh[0] = __floats2half2_rn(r0, r1);
        hh[1] = __floats2half2_rn(r2, r3);
    }
}

// ---------------- 5a) hop-1 SpMM (half2 gathers from g_Hh1, width 256) ------
// 128 threads/row; thread t owns column pair (2t, 2t+1). gridDim.y: 0=A1, 1=A2.
// fp32 result -> g_H; half copy -> g_Hh2 (hop-2 input). 16-deep load batches.
__global__ void k_spmm1() {
    int i = blockIdx.x;
    int t = threadIdx.x;                 // 0..127
    int useA2 = blockIdx.y;
    const uint16_t* __restrict__ adj  = useA2 ? g_adj2 : g_adj1;
    const int       astr = useA2 ? ADJ2_STRIDE : ADJ1_STRIDE;
    const int* __restrict__   cnt  = useA2 ? g_cnt2 : g_cnt1;
    const float* __restrict__ dinv = useA2 ? g_dinv2 : g_dinv1;
    int out_off = useA2 ? 512 : 256;

    float si = dinv[i];
    float a0 = 0.f, a1 = 0.f;

    if (si != 0.f) {
        int n = cnt[i];
        const uint16_t* __restrict__ a = adj + (size_t)i * astr;
        const __half2* __restrict__ base =
            reinterpret_cast<const __half2*>(g_Hh1) + t;   // row stride 128 half2
        int k = 0;
        for (; k + 16 <= n; k += 16) {
            int     j[16];
            float   c[16];
            __half2 v[16];
            #pragma unroll
            for (int u = 0; u < 16; u++) j[u] = a[k + u];
            #pragma unroll
            for (int u = 0; u < 16; u++) { c[u] = dinv[j[u]]; v[u] = base[j[u] * 128]; }
            #pragma unroll
            for (int u = 0; u < 16; u++) {
                float2 f = __half22float2(v[u]);
                a0 += c[u] * f.x;
                a1 += c[u] * f.y;
            }
        }
        for (; k < n; k++) {
            int jj = a[k];
            float cc = dinv[jj];
            float2 f = __half22float2(base[jj * 128]);
            a0 += cc * f.x;
            a1 += cc * f.y;
        }
        a0 *= si; a1 *= si;
    }
    a0 = fmaxf(a0, 0.f);
    a1 = fmaxf(a1, 0.f);
    // fp32 out (float2-aligned: offsets even)
    float2* o = reinterpret_cast<float2*>(g_H + (size_t)i * HSTRIDE + out_off) + t;
    *o = make_float2(a0, a1);
    // half copy for hop2 input: A1 -> pairs [0,128), A2 -> pairs [128,256)
    __half2* hh = reinterpret_cast<__half2*>(g_Hh2) + (size_t)i * 256 + (useA2 ? 128 + t : t);
    *hh = __floats2half2_rn(a0, a1);
}

// ---------------- 5b) hop-2 SpMM (half2 gathers from g_Hh2, width 512) ------
// 128 threads/row; thread t owns pairs t and t+128 (cols 2t,2t+1, 256+2t, 256+2t+1).
__global__ void k_spmm2() {
    int i = blockIdx.x;
    int t = threadIdx.x;                 // 0..127
    int useA2 = blockIdx.y;
    const uint16_t* __restrict__ adj  = useA2 ? g_adj2 : g_adj1;
    const int       astr = useA2 ? ADJ2_STRIDE : ADJ1_STRIDE;
    const int* __restrict__   cnt  = useA2 ? g_cnt2 : g_cnt1;
    const float* __restrict__ dinv = useA2 ? g_dinv2 : g_dinv1;
    int out_off = useA2 ? 1280 : 768;

    float si = dinv[i];
    float a0 = 0.f, a1 = 0.f, a2 = 0.f, a3 = 0.f;

    if (si != 0.f) {
        int n = cnt[i];
        const uint16_t* __restrict__ a = adj + (size_t)i * astr;
        const __half2* __restrict__ base =
            reinterpret_cast<const __half2*>(g_Hh2) + t;   // row stride 256 half2
        int k = 0;
        for (; k + 8 <= n; k += 8) {
            int     j[8];
            float   c[8];
            __half2 v0[8], v1[8];
            #pragma unroll
            for (int u = 0; u < 8; u++) j[u] = a[k + u];
            #pragma unroll
            for (int u = 0; u < 8; u++) {
                c[u]  = dinv[j[u]];
                const __half2* p = base + j[u] * 256;
                v0[u] = p[0];
                v1[u] = p[128];
            }
            #pragma unroll
            for (int u = 0; u < 8; u++) {
                float2 f0 = __half22float2(v0[u]);
                float2 f1 = __half22float2(v1[u]);
                a0 += c[u] * f0.x;
                a1 += c[u] * f0.y;
                a2 += c[u] * f1.x;
                a3 += c[u] * f1.y;
            }
        }
        for (; k < n; k++) {
            int jj = a[k];
            float cc = dinv[jj];
            const __half2* p = base + jj * 256;
            float2 f0 = __half22float2(p[0]);
            float2 f1 = __half22float2(p[128]);
            a0 += cc * f0.x;
            a1 += cc * f0.y;
            a2 += cc * f1.x;
            a3 += cc * f1.y;
        }
        a0 *= si; a1 *= si; a2 *= si; a3 *= si;
    }
    float2* oA = reinterpret_cast<float2*>(g_H + (size_t)i * HSTRIDE + out_off) + t;
    float2* oB = reinterpret_cast<float2*>(g_H + (size_t)i * HSTRIDE + out_off + 256) + t;
    *oA = make_float2(fmaxf(a0, 0.f), fmaxf(a1, 0.f));
    *oB = make_float2(fmaxf(a2, 0.f), fmaxf(a3, 0.f));
}

// ---------------- 6) mean pool ----------------------------------------------
__global__ void k_pool() {
    int g = blockIdx.x;
    int c = blockIdx.y * 256 + threadIdx.x;   // 7 * 256 = 1792 exactly
    int s = g_start[g], e = g_end[g];
    const float* __restrict__ H = g_H;
    float sum = 0.f;
    int cnt = 0;
    if (e > s) {
        cnt = e - s;
        for (int i = s; i < e; i++) sum += H[(size_t)i * HSTRIDE + c];
    }
    g_pool[g * HSTRIDE + c] = sum / (float)(cnt > 0 ? cnt : 1);
}

// ---------------- 7) output GEMM + bias + loss tail -------------------------
__global__ void k_out(const float* __restrict__ Wo, const float* __restrict__ bo,
                      float* __restrict__ out) {
    int g = blockIdx.x;
    int h = threadIdx.x;
    float acc = bo[h];
    const float* pg = g_pool + g * HSTRIDE;
    #pragma unroll 4
    for (int d = 0; d < HSTRIDE; d++)
        acc += pg[d] * Wo[(size_t)d * HID + h];
    out[g * HID + h] = acc;
}

__global__ void k_tail(float* out, int out_size) {
    for (int idx = NGRAPH * HID + threadIdx.x; idx < out_size; idx += 256)
        out[idx] = 0.f;   // additional_loss = 0.0 (and any padding)
}

// ---------------- launch ----------------------------------------------------
extern "C" void kernel_launch(void* const* d_in, const int* in_sizes, int n_in,
                              void* d_out, int out_size) {
    // Map inputs by element count (all counts are distinct) for robustness.
    const float* x = nullptr; const float* we = nullptr;
    const float* Wo = nullptr; const float* bo = nullptr;
    const int* ei = nullptr; const int* bat = nullptr;
    for (int i = 0; i < n_in; i++) {
        switch (in_sizes[i]) {
            case N_NODES * FEAT:   x  = (const float*)d_in[i]; break; // 4194304
            case 2 * N_EDGES:      ei = (const int*)d_in[i];   break; // 262144
            case N_NODES:          bat = (const int*)d_in[i];  break; // 8192
            case FEAT * HID:       we = (const float*)d_in[i]; break; // 131072
            case HSTRIDE * HID:    Wo = (const float*)d_in[i]; break; // 458752
            case HID:              bo = (const float*)d_in[i]; break; // 256
            default: break;
        }
    }
    float* out = (float*)d_out;

    k_setup<<<4096, 256>>>(ei, bat);
    k_scatter<<<N_EDGES / 256, 256>>>(ei, bat);
    k_build<<<N_NODES, 256>>>();
    k_embed<<<dim3(N_NODES / 64, HID / 64), 256>>>(x, we);

    // hop 1: half2 gathers from g_Hh1; y=0 -> A1 (out 256), y=1 -> A2 (out 512)
    k_spmm1<<<dim3(N_NODES, 2), 128>>>();
    // hop 2: half2 gathers from g_Hh2; y=0 -> A1 (out 768), y=1 -> A2 (out 1280)
    k_spmm2<<<dim3(N_NODES, 2), 128>>>();

    k_pool<<<dim3(NGRAPH, HSTRIDE / 256), 256>>>();
    k_out<<<NGRAPH, HID>>>(Wo, bo, out);
    k_tail<<<1, 256>>>(out, out_size);
}

// round 12
// speedup vs baseline: 2.2453x; 1.0356x over previous
#include <cuda_runtime.h>
#include <cuda_fp16.h>
#include <cstdint>

#define N_NODES   8192
#define N_EDGES   131072
#define FEAT      512
#define HID       256
#define NGRAPH    64
#define HSTRIDE   1792              // total h_node width: 256 + 512 + 1024
#define WORDS     256               // 8192 bits / 32
#define ADJ1_STRIDE 160
#define ADJ2_STRIDE 2048
#define NB_CAP    2048              // compacted 1-hop list capacity (smem)

// ---------------- static device scratch (no allocations allowed) -------------
__device__ unsigned int g_bits[N_NODES * WORDS];          // adjacency bitset (count>=1)
__device__ int          g_selfcnt[N_NODES];               // self-loop multiplicity
__device__ float        g_dinv1[N_NODES];
__device__ float        g_dinv2[N_NODES];
__device__ int          g_cnt1[N_NODES];
__device__ int          g_cnt2[N_NODES];
__device__ uint16_t     g_adj1[N_NODES * ADJ1_STRIDE];    // 1-hop neighbor lists
__device__ uint16_t     g_adj2[(size_t)N_NODES * ADJ2_STRIDE]; // strict 2-hop lists
__device__ float        g_H[(size_t)N_NODES * HSTRIDE];   // fp32 [r0 | h1a h1b | h2a h2b]
__device__ __half       g_Hh1[(size_t)N_NODES * 256];     // half copy of r0 (hop1 input)
__device__ __half       g_Hh2[(size_t)N_NODES * 512];     // half copy of hop1 out (hop2 input)
__device__ float        g_pool[NGRAPH * HSTRIDE];
__device__ int          g_start[NGRAPH];
__device__ int          g_end[NGRAPH];
__device__ int          g_ei64;                           // edge_index is int64
__device__ int          g_bat64;                          // batch is int64

// ---------------- 1) setup: dtype detection + clear accumulators ------------
// int64 arrays with values < 8192 have every odd little-endian 32-bit word 0.
__global__ void k_setup(const int* __restrict__ ei, const int* __restrict__ bat) {
    int idx = blockIdx.x * blockDim.x + threadIdx.x;
    if (idx == 0) {
        int ok = 1;
        for (int k = 0; k < 128; k++)
            if (ei[2 * k + 1] != 0) { ok = 0; break; }
        g_ei64 = ok;
        ok = 1;
        for (int k = 0; k < 128; k++)
            if (bat[2 * k + 1] != 0) { ok = 0; break; }
        g_bat64 = ok;
    }
    int stride = gridDim.x * blockDim.x;
    for (int i = idx; i < N_NODES * WORDS; i += stride) g_bits[i] = 0u;
    if (idx < N_NODES) g_selfcnt[idx] = 0;
    if (idx < NGRAPH) { g_start[idx] = 0x7fffffff; g_end[idx] = 0; }
}

// ---------------- 2) scatter edges into bitset + segment bounds -------------
__global__ void k_scatter(const int* __restrict__ ei, const int* __restrict__ bat) {
    int e = blockIdx.x * blockDim.x + threadIdx.x;
    if (e < N_EDGES) {
        int r, c;
        if (g_ei64) {
            r = ei[2 * e];                    // low word of int64
            c = ei[2 * (N_EDGES + e)];
        } else {
            r = ei[e];
            c = ei[N_EDGES + e];
        }
        if ((unsigned)r < N_NODES && (unsigned)c < N_NODES) {   // safety
            atomicOr(&g_bits[r * WORDS + (c >> 5)], 1u << (c & 31));
            if (r == c) atomicAdd(&g_selfcnt[r], 1);
        }
    }
    if (e < N_NODES) {
        int g = g_bat64 ? bat[2 * e] : bat[e];
        if ((unsigned)g < NGRAPH) {
            atomicMin(&g_start[g], e);
            atomicMax(&g_end[g], e + 1);
        }
    }
}

// ---------------- 3) boolean A@A, masks, degrees, CSR lists -----------------
// One block per row i. Thread t owns bit-word t (columns t*32..t*32+31).
// Neighbor ids are compacted to smem once (order-free: consumed only by OR),
// so the OR-gather loop avoids the per-thread 256-word rescan.
__global__ void k_build() {
    int i = blockIdx.x;
    int t = threadIdx.x;
    __shared__ unsigned int sh[WORDS];
    __shared__ int pc1[256], pc2[256];
    __shared__ uint16_t nb[NB_CAP];
    __shared__ int nb_cnt;

    sh[t] = g_bits[i * WORDS + t];
    if (t == 0) nb_cnt = 0;
    __syncthreads();

    // compact neighbor list (order nondeterministic, OR is order-free)
    {
        unsigned int b = sh[t];
        int n = __popc(b);
        int pos = (n > 0) ? atomicAdd(&nb_cnt, n) : 0;
        while (b) {
            int bit = __ffs(b) - 1; b &= b - 1;
            if (pos < NB_CAP) nb[pos] = (uint16_t)((t << 5) + bit);
            pos++;
        }
    }
    __syncthreads();

    // acc = OR over k in row(i) of row(k)  ==  indicator of (A@A) > 0
    unsigned int acc = 0u;
    int m = nb_cnt;
    if (m <= NB_CAP) {
        int k = 0;
        for (; k + 4 <= m; k += 4) {
            int k0 = nb[k], k1 = nb[k + 1], k2 = nb[k + 2], k3 = nb[k + 3];
            unsigned int a0 = g_bits[k0 * WORDS + t];
            unsigned int a1 = g_bits[k1 * WORDS + t];
            unsigned int a2 = g_bits[k2 * WORDS + t];
            unsigned int a3 = g_bits[k3 * WORDS + t];
            acc |= a0 | a1 | a2 | a3;
        }
        for (; k < m; k++) acc |= g_bits[nb[k] * WORDS + t];
    } else {
        // exact fallback for pathological degree > NB_CAP
        for (int w = 0; w < WORDS; w++) {
            unsigned int bits = sh[w];
            while (bits) {
                int b = __ffs(bits) - 1; bits &= bits - 1;
                acc |= g_bits[((w << 5) + b) * WORDS + t];
            }
        }
    }

    unsigned int myb  = sh[t];
    unsigned int diag = ((i >> 5) == t) ? (1u << (i & 31)) : 0u;

    // A1 = (A - I) > 0 : off-diag where count>=1; diagonal only if selfcount>=2
    unsigned int b1 = myb;
    if (g_selfcnt[i] < 2) b1 &= ~diag;
    // A2 = (ind(A@A) - A - I) > 0 : 2-hop reachable, no direct edge, not diagonal
    unsigned int b2 = acc & ~myb & ~diag;

    pc1[t] = __popc(b1);
    pc2[t] = __popc(b2);
    __syncthreads();

    // deterministic exclusive prefix (keeps adjacency order fixed run-to-run)
    int o1 = 0, o2 = 0;
    for (int u = 0; u < t; u++) { o1 += pc1[u]; o2 += pc2[u]; }

    unsigned int bb = b1; int p = o1;
    while (bb) {
        int b = __ffs(bb) - 1; bb &= bb - 1;
        if (p < ADJ1_STRIDE) g_adj1[i * ADJ1_STRIDE + p] = (uint16_t)((t << 5) + b);
        p++;
    }
    bb = b2; p = o2;
    while (bb) {
        int b = __ffs(bb) - 1; bb &= bb - 1;
        if (p < ADJ2_STRIDE) g_adj2[(size_t)i * ADJ2_STRIDE + p] = (uint16_t)((t << 5) + b);
        p++;
    }

    if (t == 255) {
        int c1 = o1 + pc1[255]; if (c1 > ADJ1_STRIDE) c1 = ADJ1_STRIDE;
        int c2 = o2 + pc2[255]; if (c2 > ADJ2_STRIDE) c2 = ADJ2_STRIDE;
        g_cnt1[i] = c1;
        g_cnt2[i] = c2;
        g_dinv1[i] = (c1 > 0) ? rsqrtf((float)c1) : 0.f;
        g_dinv2[i] = (c2 > 0) ? rsqrtf((float)c2) : 0.f;
    }
}

// ---------------- 4) embed GEMM: H[:,0:256] = relu(x @ w_embed) -------------
// 128x128 tile, 256 threads, 8x8 register microtile, BK=16, float4 loads.
// Per kk: 4x LDS.128 feed 64 FMA (ratio 4) -- LSU no longer the issue limiter.
// Writes fp32 into g_H and a half copy into g_Hh1 (hop1 input).
#define EBM 128
#define EBN 128
#define EBK 16
__global__ __launch_bounds__(256) void k_embed(const float* __restrict__ x,
                                               const float* __restrict__ w) {
    __shared__ float As[EBK][EBM + 4];   // row 132 floats = 528B (16B aligned)
    __shared__ float Bs[EBK][EBN];
    int t  = threadIdx.x;
    int tx = t & 15;          // n dim (8 cols each)
    int ty = t >> 4;          // m dim (8 rows each)
    int row0 = blockIdx.x * EBM;
    int col0 = blockIdx.y * EBN;

    float acc[8][8];
    #pragma unroll
    for (int u = 0; u < 8; u++)
        #pragma unroll
        for (int v = 0; v < 8; v++) acc[u][v] = 0.f;

    for (int k0 = 0; k0 < FEAT; k0 += EBK) {
        // load A tile: 128 rows x 16 k = 512 float4 (2 per thread)
        #pragma unroll
        for (int l = t; l < 512; l += 256) {
            int m = l >> 2, q = (l & 3) << 2;
            float4 v = *reinterpret_cast<const float4*>(
                &x[(size_t)(row0 + m) * FEAT + k0 + q]);
            As[q + 0][m] = v.x;
            As[q + 1][m] = v.y;
            As[q + 2][m] = v.z;
            As[q + 3][m] = v.w;
        }
        // load B tile: 16 k x 128 cols = 512 float4 (2 per thread)
        #pragma unroll
        for (int l = t; l < 512; l += 256) {
            int kk = l >> 5, n4 = (l & 31) << 2;
            *reinterpret_cast<float4*>(&Bs[kk][n4]) =
                *reinterpret_cast<const float4*>(
                    &w[(size_t)(k0 + kk) * HID + col0 + n4]);
        }
        __syncthreads();
        #pragma unroll
        for (int kk = 0; kk < EBK; kk++) {
            float a[8], b[8];
            #pragma unroll
            for (int u = 0; u < 8; u++) a[u] = As[kk][ty * 8 + u];
            #pragma unroll
            for (int v = 0; v < 8; v++) b[v] = Bs[kk][tx * 8 + v];
            #pragma unroll
            for (int u = 0; u < 8; u++)
                #pragma unroll
                for (int v = 0; v < 8; v++) acc[u][v] += a[u] * b[v];
        }
        __syncthreads();
    }
    #pragma unroll
    for (int u = 0; u < 8; u++) {
        int r = row0 + ty * 8 + u;
        int c = col0 + tx * 8;
        float rr[8];
        #pragma unroll
        for (int v = 0; v < 8; v++) rr[v] = fmaxf(acc[u][v], 0.f);
        float* o = g_H + (size_t)r * HSTRIDE + c;
        *reinterpret_cast<float4*>(o)     = make_float4(rr[0], rr[1], rr[2], rr[3]);
        *reinterpret_cast<float4*>(o + 4) = make_float4(rr[4], rr[5], rr[6], rr[7]);
        __half2* hh = reinterpret_cast<__half2*>(&g_Hh1[(size_t)r * 256 + c]);
        hh[0] = __floats2half2_rn(rr[0], rr[1]);
        hh[1] = __floats2half2_rn(rr[2], rr[3]);
        hh[2] = __floats2half2_rn(rr[4], rr[5]);
        hh[3] = __floats2half2_rn(rr[6], rr[7]);
    }
}

// ---------------- 5a) hop-1 SpMM (half2 gathers from g_Hh1, width 256) ------
// 128 threads/row; thread t owns column pair (2t, 2t+1). gridDim.y: 0=A1, 1=A2.
// fp32 result -> g_H; half copy -> g_Hh2 (hop-2 input). 16-deep load batches.
__global__ void k_spmm1() {
    int i = blockIdx.x;
    int t = threadIdx.x;                 // 0..127
    int useA2 = blockIdx.y;
    const uint16_t* __restrict__ adj  = useA2 ? g_adj2 : g_adj1;
    const int       astr = useA2 ? ADJ2_STRIDE : ADJ1_STRIDE;
    const int* __restrict__   cnt  = useA2 ? g_cnt2 : g_cnt1;
    const float* __restrict__ dinv = useA2 ? g_dinv2 : g_dinv1;
    int out_off = useA2 ? 512 : 256;

    float si = dinv[i];
    float a0 = 0.f, a1 = 0.f;

    if (si != 0.f) {
        int n = cnt[i];
        const uint16_t* __restrict__ a = adj + (size_t)i * astr;
        const __half2* __restrict__ base =
            reinterpret_cast<const __half2*>(g_Hh1) + t;   // row stride 128 half2
        int k = 0;
        for (; k + 16 <= n; k += 16) {
            int     j[16];
            float   c[16];
            __half2 v[16];
            #pragma unroll
            for (int u = 0; u < 16; u++) j[u] = a[k + u];
            #pragma unroll
            for (int u = 0; u < 16; u++) { c[u] = dinv[j[u]]; v[u] = base[j[u] * 128]; }
            #pragma unroll
            for (int u = 0; u < 16; u++) {
                float2 f = __half22float2(v[u]);
                a0 += c[u] * f.x;
                a1 += c[u] * f.y;
            }
        }
        for (; k < n; k++) {
            int jj = a[k];
            float cc = dinv[jj];
            float2 f = __half22float2(base[jj * 128]);
            a0 += cc * f.x;
            a1 += cc * f.y;
        }
        a0 *= si; a1 *= si;
    }
    a0 = fmaxf(a0, 0.f);
    a1 = fmaxf(a1, 0.f);
    // fp32 out (float2-aligned: offsets even)
    float2* o = reinterpret_cast<float2*>(g_H + (size_t)i * HSTRIDE + out_off) + t;
    *o = make_float2(a0, a1);
    // half copy for hop2 input: A1 -> pairs [0,128), A2 -> pairs [128,256)
    __half2* hh = reinterpret_cast<__half2*>(g_Hh2) + (size_t)i * 256 + (useA2 ? 128 + t : t);
    *hh = __floats2half2_rn(a0, a1);
}

// ---------------- 5b) hop-2 SpMM (half2 gathers from g_Hh2, width 512) ------
// 128 threads/row; thread t owns pairs t and t+128 (cols 2t,2t+1, 256+2t, 256+2t+1).
__global__ void k_spmm2() {
    int i = blockIdx.x;
    int t = threadIdx.x;                 // 0..127
    int useA2 = blockIdx.y;
    const uint16_t* __restrict__ adj  = useA2 ? g_adj2 : g_adj1;
    const int       astr = useA2 ? ADJ2_STRIDE : ADJ1_STRIDE;
    const int* __restrict__   cnt  = useA2 ? g_cnt2 : g_cnt1;
    const float* __restrict__ dinv = useA2 ? g_dinv2 : g_dinv1;
    int out_off = useA2 ? 1280 : 768;

    float si = dinv[i];
    float a0 = 0.f, a1 = 0.f, a2 = 0.f, a3 = 0.f;

    if (si != 0.f) {
        int n = cnt[i];
        const uint16_t* __restrict__ a = adj + (size_t)i * astr;
        const __half2* __restrict__ base =
            reinterpret_cast<const __half2*>(g_Hh2) + t;   // row stride 256 half2
        int k = 0;
        for (; k + 8 <= n; k += 8) {
            int     j[8];
            float   c[8];
            __half2 v0[8], v1[8];
            #pragma unroll
            for (int u = 0; u < 8; u++) j[u] = a[k + u];
            #pragma unroll
            for (int u = 0; u < 8; u++) {
                c[u]  = dinv[j[u]];
                const __half2* p = base + j[u] * 256;
                v0[u] = p[0];
                v1[u] = p[128];
            }
            #pragma unroll
            for (int u = 0; u < 8; u++) {
                float2 f0 = __half22float2(v0[u]);
                float2 f1 = __half22float2(v1[u]);
                a0 += c[u] * f0.x;
                a1 += c[u] * f0.y;
                a2 += c[u] * f1.x;
                a3 += c[u] * f1.y;
            }
        }
        for (; k < n; k++) {
            int jj = a[k];
            float cc = dinv[jj];
            const __half2* p = base + jj * 256;
            float2 f0 = __half22float2(p[0]);
            float2 f1 = __half22float2(p[128]);
            a0 += cc * f0.x;
            a1 += cc * f0.y;
            a2 += cc * f1.x;
            a3 += cc * f1.y;
        }
        a0 *= si; a1 *= si; a2 *= si; a3 *= si;
    }
    float2* oA = reinterpret_cast<float2*>(g_H + (size_t)i * HSTRIDE + out_off) + t;
    float2* oB = reinterpret_cast<float2*>(g_H + (size_t)i * HSTRIDE + out_off + 256) + t;
    *oA = make_float2(fmaxf(a0, 0.f), fmaxf(a1, 0.f));
    *oB = make_float2(fmaxf(a2, 0.f), fmaxf(a3, 0.f));
}

// ---------------- 6) mean pool ----------------------------------------------
__global__ void k_pool() {
    int g = blockIdx.x;
    int c = blockIdx.y * 256 + threadIdx.x;   // 7 * 256 = 1792 exactly
    int s = g_start[g], e = g_end[g];
    const float* __restrict__ H = g_H;
    float sum = 0.f;
    int cnt = 0;
    if (e > s) {
        cnt = e - s;
        for (int i = s; i < e; i++) sum += H[(size_t)i * HSTRIDE + c];
    }
    g_pool[g * HSTRIDE + c] = sum / (float)(cnt > 0 ? cnt : 1);
}

// ---------------- 7) output GEMM + bias + loss tail -------------------------
__global__ void k_out(const float* __restrict__ Wo, const float* __restrict__ bo,
                      float* __restrict__ out) {
    int g = blockIdx.x;
    int h = threadIdx.x;
    float acc = bo[h];
    const float* pg = g_pool + g * HSTRIDE;
    #pragma unroll 4
    for (int d = 0; d < HSTRIDE; d++)
        acc += pg[d] * Wo[(size_t)d * HID + h];
    out[g * HID + h] = acc;
}

__global__ void k_tail(float* out, int out_size) {
    for (int idx = NGRAPH * HID + threadIdx.x; idx < out_size; idx += 256)
        out[idx] = 0.f;   // additional_loss = 0.0 (and any padding)
}

// ---------------- launch ----------------------------------------------------
extern "C" void kernel_launch(void* const* d_in, const int* in_sizes, int n_in,
                              void* d_out, int out_size) {
    // Map inputs by element count (all counts are distinct) for robustness.
    const float* x = nullptr; const float* we = nullptr;
    const float* Wo = nullptr; const float* bo = nullptr;
    const int* ei = nullptr; const int* bat = nullptr;
    for (int i = 0; i < n_in; i++) {
        switch (in_sizes[i]) {
            case N_NODES * FEAT:   x  = (const float*)d_in[i]; break; // 4194304
            case 2 * N_EDGES:      ei = (const int*)d_in[i];   break; // 262144
            case N_NODES:          bat = (const int*)d_in[i];  break; // 8192
            case FEAT * HID:       we = (const float*)d_in[i]; break; // 131072
            case HSTRIDE * HID:    Wo = (const float*)d_in[i]; break; // 458752
            case HID:              bo = (const float*)d_in[i]; break; // 256
            default: break;
        }
    }
    float* out = (float*)d_out;

    k_setup<<<4096, 256>>>(ei, bat);
    k_scatter<<<N_EDGES / 256, 256>>>(ei, bat);
    k_build<<<N_NODES, 256>>>();
    k_embed<<<dim3(N_NODES / EBM, HID / EBN), 256>>>(x, we);

    // hop 1: half2 gathers from g_Hh1; y=0 -> A1 (out 256), y=1 -> A2 (out 512)
    k_spmm1<<<dim3(N_NODES, 2), 128>>>();
    // hop 2: half2 gathers from g_Hh2; y=0 -> A1 (out 768), y=1 -> A2 (out 1280)
    k_spmm2<<<dim3(N_NODES, 2), 128>>>();

    k_pool<<<dim3(NGRAPH, HSTRIDE / 256), 256>>>();
    k_out<<<NGRAPH, HID>>>(Wo, bo, out);
    k_tail<<<1, 256>>>(out, out_size);
}

// round 17
// speedup vs baseline: 2.3657x; 1.0536x over previous
#include <cuda_runtime.h>
#include <cuda_fp16.h>
#include <cstdint>

#define N_NODES   8192
#define N_EDGES   131072
#define FEAT      512
#define HID       256
#define NGRAPH    64
#define HSTRIDE   1792              // total h_node width: 256 + 512 + 1024
#define WORDS     256               // 8192 bits / 32
#define ADJ1_STRIDE 160
#define ADJ2_STRIDE 2048
#define NB_CAP    2048              // compacted 1-hop list capacity (smem)

// ---------------- static device scratch (no allocations allowed) -------------
__device__ unsigned int g_bits[N_NODES * WORDS];          // adjacency bitset (count>=1)
__device__ int          g_selfcnt[N_NODES];               // self-loop multiplicity
__device__ float        g_dinv1[N_NODES];
__device__ float        g_dinv2[N_NODES];
__device__ int          g_cnt1[N_NODES];
__device__ int          g_cnt2[N_NODES];
__device__ uint16_t     g_adj1[N_NODES * ADJ1_STRIDE];    // 1-hop neighbor lists
__device__ uint16_t     g_adj2[(size_t)N_NODES * ADJ2_STRIDE]; // strict 2-hop lists
__device__ float        g_H[(size_t)N_NODES * HSTRIDE];   // fp32 [r0 | h1a h1b | h2a h2b]
__device__ __half       g_Hh1[(size_t)N_NODES * 256];     // half copy of r0 (hop1 input)
__device__ __half       g_Hh2[(size_t)N_NODES * 512];     // half copy of hop1 out (hop2 input)
__device__ float        g_pool[NGRAPH * HSTRIDE];
__device__ int          g_start[NGRAPH];
__device__ int          g_end[NGRAPH];
__device__ int          g_ei64;                           // edge_index is int64
__device__ int          g_bat64;                          // batch is int64

// ---------------- 1) setup: dtype detection + clear accumulators ------------
// int64 arrays with values < 8192 have every odd little-endian 32-bit word 0.
__global__ void k_setup(const int* __restrict__ ei, const int* __restrict__ bat) {
    int idx = blockIdx.x * blockDim.x + threadIdx.x;
    if (idx == 0) {
        int ok = 1;
        for (int k = 0; k < 128; k++)
            if (ei[2 * k + 1] != 0) { ok = 0; break; }
        g_ei64 = ok;
        ok = 1;
        for (int k = 0; k < 128; k++)
            if (bat[2 * k + 1] != 0) { ok = 0; break; }
        g_bat64 = ok;
    }
    int stride = gridDim.x * blockDim.x;
    for (int i = idx; i < N_NODES * WORDS; i += stride) g_bits[i] = 0u;
    if (idx < N_NODES) g_selfcnt[idx] = 0;
    if (idx < NGRAPH) { g_start[idx] = 0x7fffffff; g_end[idx] = 0; }
}

// ---------------- 2) scatter edges into bitset + segment bounds -------------
__global__ void k_scatter(const int* __restrict__ ei, const int* __restrict__ bat) {
    int e = blockIdx.x * blockDim.x + threadIdx.x;
    if (e < N_EDGES) {
        int r, c;
        if (g_ei64) {
            r = ei[2 * e];                    // low word of int64
            c = ei[2 * (N_EDGES + e)];
        } else {
            r = ei[e];
            c = ei[N_EDGES + e];
        }
        if ((unsigned)r < N_NODES && (unsigned)c < N_NODES) {   // safety
            atomicOr(&g_bits[r * WORDS + (c >> 5)], 1u << (c & 31));
            if (r == c) atomicAdd(&g_selfcnt[r], 1);
        }
    }
    if (e < N_NODES) {
        int g = g_bat64 ? bat[2 * e] : bat[e];
        if ((unsigned)g < NGRAPH) {
            atomicMin(&g_start[g], e);
            atomicMax(&g_end[g], e + 1);
        }
    }
}

// ---------------- 3) boolean A@A, masks, degrees, CSR lists -----------------
// One block per row i. Thread t owns bit-word t (columns t*32..t*32+31).
// Neighbor ids are compacted to smem once (order-free: consumed only by OR),
// so the OR-gather loop avoids the per-thread 256-word rescan.
__global__ void k_build() {
    int i = blockIdx.x;
    int t = threadIdx.x;
    __shared__ unsigned int sh[WORDS];
    __shared__ int pc1[256], pc2[256];
    __shared__ uint16_t nb[NB_CAP];
    __shared__ int nb_cnt;

    sh[t] = g_bits[i * WORDS + t];
    if (t == 0) nb_cnt = 0;
    __syncthreads();

    // compact neighbor list (order nondeterministic, OR is order-free)
    {
        unsigned int b = sh[t];
        int n = __popc(b);
        int pos = (n > 0) ? atomicAdd(&nb_cnt, n) : 0;
        while (b) {
            int bit = __ffs(b) - 1; b &= b - 1;
            if (pos < NB_CAP) nb[pos] = (uint16_t)((t << 5) + bit);
            pos++;
        }
    }
    __syncthreads();

    // acc = OR over k in row(i) of row(k)  ==  indicator of (A@A) > 0
    unsigned int acc = 0u;
    int m = nb_cnt;
    if (m <= NB_CAP) {
        int k = 0;
        for (; k + 4 <= m; k += 4) {
            int k0 = nb[k], k1 = nb[k + 1], k2 = nb[k + 2], k3 = nb[k + 3];
            unsigned int a0 = g_bits[k0 * WORDS + t];
            unsigned int a1 = g_bits[k1 * WORDS + t];
            unsigned int a2 = g_bits[k2 * WORDS + t];
            unsigned int a3 = g_bits[k3 * WORDS + t];
            acc |= a0 | a1 | a2 | a3;
        }
        for (; k < m; k++) acc |= g_bits[nb[k] * WORDS + t];
    } else {
        // exact fallback for pathological degree > NB_CAP
        for (int w = 0; w < WORDS; w++) {
            unsigned int bits = sh[w];
            while (bits) {
                int b = __ffs(bits) - 1; bits &= bits - 1;
                acc |= g_bits[((w << 5) + b) * WORDS + t];
            }
        }
    }

    unsigned int myb  = sh[t];
    unsigned int diag = ((i >> 5) == t) ? (1u << (i & 31)) : 0u;

    // A1 = (A - I) > 0 : off-diag where count>=1; diagonal only if selfcount>=2
    unsigned int b1 = myb;
    if (g_selfcnt[i] < 2) b1 &= ~diag;
    // A2 = (ind(A@A) - A - I) > 0 : 2-hop reachable, no direct edge, not diagonal
    unsigned int b2 = acc & ~myb & ~diag;

    pc1[t] = __popc(b1);
    pc2[t] = __popc(b2);
    __syncthreads();

    // deterministic exclusive prefix (keeps adjacency order fixed run-to-run)
    int o1 = 0, o2 = 0;
    for (int u = 0; u < t; u++) { o1 += pc1[u]; o2 += pc2[u]; }

    unsigned int bb = b1; int p = o1;
    while (bb) {
        int b = __ffs(bb) - 1; bb &= bb - 1;
        if (p < ADJ1_STRIDE) g_adj1[i * ADJ1_STRIDE + p] = (uint16_t)((t << 5) + b);
        p++;
    }
    bb = b2; p = o2;
    while (bb) {
        int b = __ffs(bb) - 1; bb &= bb - 1;
        if (p < ADJ2_STRIDE) g_adj2[(size_t)i * ADJ2_STRIDE + p] = (uint16_t)((t << 5) + b);
        p++;
    }

    if (t == 255) {
        int c1 = o1 + pc1[255]; if (c1 > ADJ1_STRIDE) c1 = ADJ1_STRIDE;
        int c2 = o2 + pc2[255]; if (c2 > ADJ2_STRIDE) c2 = ADJ2_STRIDE;
        g_cnt1[i] = c1;
        g_cnt2[i] = c2;
        g_dinv1[i] = (c1 > 0) ? rsqrtf((float)c1) : 0.f;
        g_dinv2[i] = (c2 > 0) ? rsqrtf((float)c2) : 0.f;
    }
}

// ---------------- 4) embed GEMM: H[:,0:256] = relu(x @ w_embed) -------------
// 64x128 tile, 256 threads, 8x4 register microtile, BK=16, float4 loads.
// grid = 256 blocks (>1 wave on 148 SMs); ~32 acc regs keeps occupancy up.
// Writes fp32 into g_H and a half copy into g_Hh1 (hop1 input).
#define EBM 64
#define EBN 128
#define EBK 16
__global__ __launch_bounds__(256) void k_embed(const float* __restrict__ x,
                                               const float* __restrict__ w) {
    __shared__ float As[EBK][EBM + 4];
    __shared__ float Bs[EBK][EBN];
    int t  = threadIdx.x;
    int tx = t & 31;          // n dim: 4 cols each (32*4 = 128)
    int ty = t >> 5;          // m dim: 8 rows each (8*8 = 64)
    int row0 = blockIdx.x * EBM;
    int col0 = blockIdx.y * EBN;

    float acc[8][4];
    #pragma unroll
    for (int u = 0; u < 8; u++)
        #pragma unroll
        for (int v = 0; v < 4; v++) acc[u][v] = 0.f;

    for (int k0 = 0; k0 < FEAT; k0 += EBK) {
        // A tile: 64 rows x 16 k = 256 float4 (1 per thread)
        {
            int m = t >> 2, q = (t & 3) << 2;
            float4 v = *reinterpret_cast<const float4*>(
                &x[(size_t)(row0 + m) * FEAT + k0 + q]);
            As[q + 0][m] = v.x;
            As[q + 1][m] = v.y;
            As[q + 2][m] = v.z;
            As[q + 3][m] = v.w;
        }
        // B tile: 16 k x 128 cols = 512 float4 (2 per thread)
        #pragma unroll
        for (int l = t; l < 512; l += 256) {
            int kk = l >> 5, n4 = (l & 31) << 2;
            *reinterpret_cast<float4*>(&Bs[kk][n4]) =
                *reinterpret_cast<const float4*>(
                    &w[(size_t)(k0 + kk) * HID + col0 + n4]);
        }
        __syncthreads();
        #pragma unroll
        for (int kk = 0; kk < EBK; kk++) {
            float a[8], b[4];
            #pragma unroll
            for (int u = 0; u < 8; u++) a[u] = As[kk][ty * 8 + u];
            #pragma unroll
            for (int v = 0; v < 4; v++) b[v] = Bs[kk][tx * 4 + v];
            #pragma unroll
            for (int u = 0; u < 8; u++)
                #pragma unroll
                for (int v = 0; v < 4; v++) acc[u][v] += a[u] * b[v];
        }
        __syncthreads();
    }
    #pragma unroll
    for (int u = 0; u < 8; u++) {
        int r = row0 + ty * 8 + u;
        int c = col0 + tx * 4;
        float r0 = fmaxf(acc[u][0], 0.f);
        float r1 = fmaxf(acc[u][1], 0.f);
        float r2 = fmaxf(acc[u][2], 0.f);
        float r3 = fmaxf(acc[u][3], 0.f);
        *reinterpret_cast<float4*>(g_H + (size_t)r * HSTRIDE + c) =
            make_float4(r0, r1, r2, r3);
        __half2* hh = reinterpret_cast<__half2*>(&g_Hh1[(size_t)r * 256 + c]);
        hh[0] = __floats2half2_rn(r0, r1);
        hh[1] = __floats2half2_rn(r2, r3);
    }
}

// ---------------- 5a) hop-1 SpMM (uint2 gathers from g_Hh1, width 256) ------
// 2 rows/block, 64 threads/row. Thread t owns cols 4t..4t+3 (one 8B LDG per
// neighbor). gridDim.y: 0=A1, 1=A2. fp32 -> g_H; half copy -> g_Hh2.
__global__ void k_spmm1() {
    int useA2 = blockIdx.y;
    int i = blockIdx.x * 2 + threadIdx.y;
    int t = threadIdx.x;                 // 0..63
    const uint16_t* __restrict__ adj  = useA2 ? g_adj2 : g_adj1;
    const int       astr = useA2 ? ADJ2_STRIDE : ADJ1_STRIDE;
    const int* __restrict__   cnt  = useA2 ? g_cnt2 : g_cnt1;
    const float* __restrict__ dinv = useA2 ? g_dinv2 : g_dinv1;
    int out_off = useA2 ? 512 : 256;

    float si = dinv[i];
    float a0 = 0.f, a1 = 0.f, a2 = 0.f, a3 = 0.f;

    if (si != 0.f) {
        int n = cnt[i];
        const uint16_t* __restrict__ a = adj + (size_t)i * astr;
        const uint2* __restrict__ base =
            reinterpret_cast<const uint2*>(g_Hh1) + t;   // row stride 64 uint2
        int k = 0;
        for (; k + 16 <= n; k += 16) {
            int   j[16];
            float c[16];
            uint2 v[16];
            #pragma unroll
            for (int u = 0; u < 16; u++) j[u] = a[k + u];
            #pragma unroll
            for (int u = 0; u < 16; u++) { c[u] = dinv[j[u]]; v[u] = base[j[u] * 64]; }
            #pragma unroll
            for (int u = 0; u < 16; u++) {
                float2 f0 = __half22float2(*reinterpret_cast<__half2*>(&v[u].x));
                float2 f1 = __half22float2(*reinterpret_cast<__half2*>(&v[u].y));
                a0 += c[u] * f0.x;
                a1 += c[u] * f0.y;
                a2 += c[u] * f1.x;
                a3 += c[u] * f1.y;
            }
        }
        for (; k < n; k++) {
            int jj = a[k];
            float cc = dinv[jj];
            uint2 v = base[jj * 64];
            float2 f0 = __half22float2(*reinterpret_cast<__half2*>(&v.x));
            float2 f1 = __half22float2(*reinterpret_cast<__half2*>(&v.y));
            a0 += cc * f0.x;
            a1 += cc * f0.y;
            a2 += cc * f1.x;
            a3 += cc * f1.y;
        }
        a0 *= si; a1 *= si; a2 *= si; a3 *= si;
    }
    a0 = fmaxf(a0, 0.f);
    a1 = fmaxf(a1, 0.f);
    a2 = fmaxf(a2, 0.f);
    a3 = fmaxf(a3, 0.f);
    // fp32 out: cols out_off+4t .. out_off+4t+3 (16B aligned)
    *reinterpret_cast<float4*>(g_H + (size_t)i * HSTRIDE + out_off + 4 * t) =
        make_float4(a0, a1, a2, a3);
    // half copy for hop2 input: A1 -> uint2 [0,64), A2 -> uint2 [64,128)
    __half2 h0 = __floats2half2_rn(a0, a1);
    __half2 h1 = __floats2half2_rn(a2, a3);
    uint2 hv;
    hv.x = *reinterpret_cast<unsigned int*>(&h0);
    hv.y = *reinterpret_cast<unsigned int*>(&h1);
    reinterpret_cast<uint2*>(g_Hh2)[(size_t)i * 128 + (useA2 ? 64 : 0) + t] = hv;
}

// ---------------- 5b) hop-2 SpMM (uint2 gathers from g_Hh2, width 512) ------
// 128 threads/row; thread t owns cols 4t..4t+3 (one 8B LDG per neighbor).
__global__ void k_spmm2() {
    int i = blockIdx.x;
    int t = threadIdx.x;                 // 0..127
    int useA2 = blockIdx.y;
    const uint16_t* __restrict__ adj  = useA2 ? g_adj2 : g_adj1;
    const int       astr = useA2 ? ADJ2_STRIDE : ADJ1_STRIDE;
    const int* __restrict__   cnt  = useA2 ? g_cnt2 : g_cnt1;
    const float* __restrict__ dinv = useA2 ? g_dinv2 : g_dinv1;
    int out_off = useA2 ? 1280 : 768;

    float si = dinv[i];
    float a0 = 0.f, a1 = 0.f, a2 = 0.f, a3 = 0.f;

    if (si != 0.f) {
        int n = cnt[i];
        const uint16_t* __restrict__ a = adj + (size_t)i * astr;
        const uint2* __restrict__ base =
            reinterpret_cast<const uint2*>(g_Hh2) + t;   // row stride 128 uint2
        int k = 0;
        for (; k + 8 <= n; k += 8) {
            int   j[8];
            float c[8];
            uint2 v[8];
            #pragma unroll
            for (int u = 0; u < 8; u++) j[u] = a[k + u];
            #pragma unroll
            for (int u = 0; u < 8; u++) { c[u] = dinv[j[u]]; v[u] = base[j[u] * 128]; }
            #pragma unroll
            for (int u = 0; u < 8; u++) {
                float2 f0 = __half22float2(*reinterpret_cast<__half2*>(&v[u].x));
                float2 f1 = __half22float2(*reinterpret_cast<__half2*>(&v[u].y));
                a0 += c[u] * f0.x;
                a1 += c[u] * f0.y;
                a2 += c[u] * f1.x;
                a3 += c[u] * f1.y;
            }
        }
        for (; k < n; k++) {
            int jj = a[k];
            float cc = dinv[jj];
            uint2 v = base[jj * 128];
            float2 f0 = __half22float2(*reinterpret_cast<__half2*>(&v.x));
            float2 f1 = __half22float2(*reinterpret_cast<__half2*>(&v.y));
            a0 += cc * f0.x;
            a1 += cc * f0.y;
            a2 += cc * f1.x;
            a3 += cc * f1.y;
        }
        a0 *= si; a1 *= si; a2 *= si; a3 *= si;
    }
    *reinterpret_cast<float4*>(g_H + (size_t)i * HSTRIDE + out_off + 4 * t) =
        make_float4(fmaxf(a0, 0.f), fmaxf(a1, 0.f), fmaxf(a2, 0.f), fmaxf(a3, 0.f));
}

// ---------------- 6) mean pool ----------------------------------------------
__global__ void k_pool() {
    int g = blockIdx.x;
    int c = blockIdx.y * 256 + threadIdx.x;   // 7 * 256 = 1792 exactly
    int s = g_start[g], e = g_end[g];
    const float* __restrict__ H = g_H;
    float sum = 0.f;
    int cnt = 0;
    if (e > s) {
        cnt = e - s;
        for (int i = s; i < e; i++) sum += H[(size_t)i * HSTRIDE + c];
    }
    g_pool[g * HSTRIDE + c] = sum / (float)(cnt > 0 ? cnt : 1);
}

// ---------------- 7) output GEMM + bias + loss tail -------------------------
__global__ void k_out(const float* __restrict__ Wo, const float* __restrict__ bo,
                      float* __restrict__ out) {
    int g = blockIdx.x;
    int h = threadIdx.x;
    float acc = bo[h];
    const float* pg = g_pool + g * HSTRIDE;
    #pragma unroll 4
    for (int d = 0; d < HSTRIDE; d++)
        acc += pg[d] * Wo[(size_t)d * HID + h];
    out[g * HID + h] = acc;
}

__global__ void k_tail(float* out, int out_size) {
    for (int idx = NGRAPH * HID + threadIdx.x; idx < out_size; idx += 256)
        out[idx] = 0.f;   // additional_loss = 0.0 (and any padding)
}

// ---------------- launch ----------------------------------------------------
extern "C" void kernel_launch(void* const* d_in, const int* in_sizes, int n_in,
                              void* d_out, int out_size) {
    // Map inputs by element count (all counts are distinct) for robustness.
    const float* x = nullptr; const float* we = nullptr;
    const float* Wo = nullptr; const float* bo = nullptr;
    const int* ei = nullptr; const int* bat = nullptr;
    for (int i = 0; i < n_in; i++) {
        switch (in_sizes[i]) {
            case N_NODES * FEAT:   x  = (const float*)d_in[i]; break; // 4194304
            case 2 * N_EDGES:      ei = (const int*)d_in[i];   break; // 262144
            case N_NODES:          bat = (const int*)d_in[i];  break; // 8192
            case FEAT * HID:       we = (const float*)d_in[i]; break; // 131072
            case HSTRIDE * HID:    Wo = (const float*)d_in[i]; break; // 458752
            case HID:              bo = (const float*)d_in[i]; break; // 256
            default: break;
        }
    }
    float* out = (float*)d_out;

    k_setup<<<4096, 256>>>(ei, bat);
    k_scatter<<<N_EDGES / 256, 256>>>(ei, bat);
    k_build<<<N_NODES, 256>>>();
    k_embed<<<dim3(N_NODES / EBM, HID / EBN), 256>>>(x, we);

    // hop 1: uint2 gathers from g_Hh1; y=0 -> A1 (out 256), y=1 -> A2 (out 512)
    k_spmm1<<<dim3(N_NODES / 2, 2), dim3(64, 2)>>>();
    // hop 2: uint2 gathers from g_Hh2; y=0 -> A1 (out 768), y=1 -> A2 (out 1280)
    k_spmm2<<<dim3(N_NODES, 2), 128>>>();

    k_pool<<<dim3(NGRAPH, HSTRIDE / 256), 256>>>();
    k_out<<<NGRAPH, HID>>>(Wo, bo, out);
    k_tail<<<1, 256>>>(out, out_size);
}